// round 16
// baseline (speedup 1.0000x reference)
#include <cuda_runtime.h>
#include <cuda_fp16.h>
#include <cstdint>

// Problem constants (fixed by the dataset)
#define BB   16
#define NN   4096
#define SS   1024
#define KK   32
#define DIN  64
#define DINC 67
#define DOUT 64

// Scratch (fp16 intermediates)
__device__ uint16_t g_sum_h[(size_t)BB * NN * DOUT];   // fp16(xc@W1 + bias (+ xp))
__device__ uint16_t g_xp_h [(size_t)BB * NN * DOUT];   // fp16(x@W2)

// ---------------------------------------------------------------------------
// SMEM layout (bytes)  [proj: 128 rows/CTA, R12 config]
// SMEM_ALLOC is padded beyond the used size to force occupancy = 2 CTAs/SM,
// turning the 512-CTA grid into 2 waves so wave-2 staging (DRAM) overlaps
// wave-1 MMA (tensor) instead of one chip-wide lock-step wave.
// ---------------------------------------------------------------------------
#define SAB   0                         // 9*128*32 = 36864
#define SBB   36864                     // 9*64*32  = 18432
#define SBIAS 55296                     // 256
#define SMEM_BYTES 55552                // bytes actually used
#define SMEM_ALLOC 115712               // padded request -> occ 2

__device__ __forceinline__ uint32_t pack_h2(float v0, float v1) {
    __half2 h = __floats2half2_rn(v0, v1);
    return *(uint32_t*)&h;
}

__device__ __forceinline__ void mma16(float* d, uint32_t a0, uint32_t a1, uint32_t a2,
                                      uint32_t a3, uint32_t b0, uint32_t b1) {
    asm volatile(
        "mma.sync.aligned.m16n8k16.row.col.f32.f16.f16.f32 "
        "{%0,%1,%2,%3}, {%4,%5,%6,%7}, {%8,%9}, {%0,%1,%2,%3};"
        : "+f"(d[0]), "+f"(d[1]), "+f"(d[2]), "+f"(d[3])
        : "r"(a0), "r"(a1), "r"(a2), "r"(a3), "r"(b0), "r"(b1));
}

__device__ __forceinline__ void gemm_phase(
    const uint2* abuf, const uint2* bbuf, int ks0, int ks1,
    float acc[2][4][4], const int rA[2], const int nI[4], int km)
{
    for (int ks = ks0; ks < ks1; ks++) {
        uint2 A0[2], A1[2], Bv[4];
        #pragma unroll
        for (int tM = 0; tM < 2; tM++) {
            int r0 = rA[tM], r1 = rA[tM] + 8;
            A0[tM] = abuf[(ks * 128 + r0) * 4 + (km ^ (r0 & 3))];
            A1[tM] = abuf[(ks * 128 + r1) * 4 + (km ^ (r1 & 3))];
        }
        #pragma unroll
        for (int tN = 0; tN < 4; tN++) {
            int n = nI[tN];
            Bv[tN] = bbuf[(ks * 64 + n) * 4 + (km ^ (n & 3))];
        }
        #pragma unroll
        for (int tM = 0; tM < 2; tM++)
            #pragma unroll
            for (int tN = 0; tN < 4; tN++)
                mma16(acc[tM][tN], A0[tM].x, A1[tM].x, A0[tM].y, A1[tM].y, Bv[tN].x, Bv[tN].y);
    }
}

// ---------------------------------------------------------------------------
// proj_mma: per CTA computes 128 rows of g_xp_h and g_sum_h via fp16 MMA.
// (R12 code; float2 loads where alignment allows)
// ---------------------------------------------------------------------------
__global__ void __launch_bounds__(256) proj_mma(
    const float* __restrict__ x, const float* __restrict__ xcm,
    const float* __restrict__ w1, const float* __restrict__ w2,
    const float* __restrict__ bias, const int* __restrict__ use_x)
{
    extern __shared__ char smem[];
    uint32_t* sA = (uint32_t*)(smem + SAB);
    uint32_t* sB = (uint32_t*)(smem + SBB);
    float*    sBias = (float*)(smem + SBIAS);

    const int tid  = threadIdx.x;
    const int wid  = tid >> 5;
    const int lane = tid & 31;
    const int ux   = use_x[0];
    const size_t base = (size_t)blockIdx.x * 128;

    // ---- stage W2 [64 n][64 k] -> B ks 0..3 (float2: rows 256B-aligned) ----
    for (int i = tid; i < 64 * 32; i += 256) {
        int n = i >> 5, jj32 = i & 31;
        int ks = jj32 >> 3, jj = jj32 & 7;
        int k0 = ks * 16 + 2 * jj;
        float2 w = *(const float2*)(w2 + n * DIN + k0);
        uint32_t p = pack_h2(w.x, w.y);
        int a2 = (ks * 64 + n) * 4 + ((jj & 3) ^ (n & 3));
        sB[a2 * 2 + (jj >> 2)] = p;
    }
    // ---- stage W1 [64 n][67 k -> 80] -> B ks 4..8 (scalar: odd row stride) --
    for (int i = tid; i < 64 * 40; i += 256) {
        int n = i / 40, jj40 = i - n * 40;
        int ksl = jj40 >> 3, jj = jj40 & 7;
        int k0 = ksl * 16 + 2 * jj;
        float v0 = (k0     < DINC) ? w1[n * DINC + k0]     : 0.0f;
        float v1 = (k0 + 1 < DINC) ? w1[n * DINC + k0 + 1] : 0.0f;
        uint32_t p = pack_h2(v0, v1);
        int ks = 4 + ksl;
        int a2 = (ks * 64 + n) * 4 + ((jj & 3) ^ (n & 3));
        sB[a2 * 2 + (jj >> 2)] = p;
    }
    if (tid < DOUT) sBias[tid] = bias[tid];
    // ---- stage x tile [128][64] -> A ks 0..3 (float2) ----
    if (ux) {
        const float* src = x + base * DIN;
        for (int i = tid; i < 128 * 32; i += 256) {
            int r = i >> 5, jj32 = i & 31;
            int ks = jj32 >> 3, jj = jj32 & 7;
            int k0 = ks * 16 + 2 * jj;
            float2 w = *(const float2*)(src + r * DIN + k0);
            uint32_t p = pack_h2(w.x, w.y);
            int a2 = (ks * 128 + r) * 4 + ((jj & 3) ^ (r & 3));
            sA[a2 * 2 + (jj >> 2)] = p;
        }
    }
    // ---- stage xc tile [128][67 -> 80] -> A ks 4..8 (scalar) ----
    {
        const float* src = xcm + base * DINC;
        for (int i = tid; i < 128 * 40; i += 256) {
            int r = i / 40, jj40 = i - r * 40;
            int ksl = jj40 >> 3, jj = jj40 & 7;
            int k0 = ksl * 16 + 2 * jj;
            float v0 = (k0     < DINC) ? src[r * DINC + k0]     : 0.0f;
            float v1 = (k0 + 1 < DINC) ? src[r * DINC + k0 + 1] : 0.0f;
            uint32_t p = pack_h2(v0, v1);
            int ks = 4 + ksl;
            int a2 = (ks * 128 + r) * 4 + ((jj & 3) ^ (r & 3));
            sA[a2 * 2 + (jj >> 2)] = p;
        }
    }
    __syncthreads();

    // ---- per-warp fragment coordinates (warp grid 4M x 2N; 32x32 per warp) --
    const int warpM = wid >> 1;
    const int warpN = wid & 1;
    const int km    = lane & 3;
    const int qr    = lane >> 2;
    int rA[2], nI[4];
    #pragma unroll
    for (int tM = 0; tM < 2; tM++) rA[tM] = warpM * 32 + tM * 16 + qr;
    #pragma unroll
    for (int tN = 0; tN < 4; tN++) nI[tN] = warpN * 32 + tN * 8 + qr;

    float acc[2][4][4];
    #pragma unroll
    for (int i = 0; i < 2; i++)
        #pragma unroll
        for (int j = 0; j < 4; j++)
            #pragma unroll
            for (int q = 0; q < 4; q++) acc[i][j][q] = 0.0f;

    const int colq = 2 * (lane & 3);

    // ---- Phase A: acc = x @ W2^T ; write g_xp_h ----
    if (ux) {
        gemm_phase((const uint2*)sA, (const uint2*)sB, 0, 4, acc, rA, nI, km);
        #pragma unroll
        for (int tM = 0; tM < 2; tM++) {
            int r = rA[tM];
            #pragma unroll
            for (int tN = 0; tN < 4; tN++) {
                int cc = warpN * 32 + tN * 8 + colq;
                uint16_t* p = g_xp_h + (base + r) * DOUT + cc;
                *(uint32_t*)p = pack_h2(acc[tM][tN][0], acc[tM][tN][1]);
                *(uint32_t*)(p + 8 * DOUT) = pack_h2(acc[tM][tN][2], acc[tM][tN][3]);
            }
        }
    }

    // ---- Phase B: acc += xc @ W1^T ; write g_sum_h = fp16(acc + bias) ----
    gemm_phase((const uint2*)sA, (const uint2*)sB, 4, 9, acc, rA, nI, km);

    #pragma unroll
    for (int tM = 0; tM < 2; tM++) {
        int r = rA[tM];
        #pragma unroll
        for (int tN = 0; tN < 4; tN++) {
            int cc = warpN * 32 + tN * 8 + colq;
            float2 bv = *(const float2*)(sBias + cc);
            uint16_t* p = g_sum_h + (base + r) * DOUT + cc;
            *(uint32_t*)p = pack_h2(acc[tM][tN][0] + bv.x, acc[tM][tN][1] + bv.y);
            *(uint32_t*)(p + 8 * DOUT) = pack_h2(acc[tM][tN][2] + bv.x, acc[tM][tN][3] + bv.y);
        }
    }
}

// ---------------------------------------------------------------------------
// Pool kernel (R12 optimum: 32 pairs/block, 8 threads/pair, uint4 + __hmax2)
// ---------------------------------------------------------------------------
__global__ void __launch_bounds__(256) pool_kernel(
    const void* __restrict__ indexes, const int* __restrict__ use_x,
    float* __restrict__ out)
{
    __shared__ int sidx[1024];          // 32 pairs x 32 idx
    const int tid = threadIdx.x;
    const size_t blk = blockIdx.x;      // 512 blocks

    // prologue: independent of proj output (in-bounds under BOTH dtypes)
    int4 v = ((const int4*)indexes)[blk * 256 + tid];
    bool pok = (v.y == (v.x < 0 ? -1 : 0)) && (v.w == (v.z < 0 ? -1 : 0));
    int is64 = __syncthreads_and(pok);

    if (is64) {
        longlong2 q0 = ((const longlong2*)indexes)[blk * 512 + 2 * tid];
        longlong2 q1 = ((const longlong2*)indexes)[blk * 512 + 2 * tid + 1];
        sidx[4 * tid]     = (int)q0.x;
        sidx[4 * tid + 1] = (int)q0.y;
        sidx[4 * tid + 2] = (int)q1.x;
        sidx[4 * tid + 3] = (int)q1.y;
    } else {
        sidx[4 * tid]     = v.x;
        sidx[4 * tid + 1] = v.y;
        sidx[4 * tid + 2] = v.z;
        sidx[4 * tid + 3] = v.w;
    }
    const int ux = use_x[0];
    __syncthreads();

    const int grp   = tid >> 3;
    const int lane8 = tid & 7;
    const size_t p  = blk * 32 + grp;
    const int b     = (int)(p >> 10);
    const int* myidx = sidx + grp * 32;
    const int c0  = lane8 * 8;
    const int id0 = myidx[0];

    // wait for proj grid completion (PDL)
    asm volatile("griddepcontrol.wait;" ::: "memory");

    const uint16_t* sumb = g_sum_h + (size_t)b * NN * DOUT;

    float cf[8];
    #pragma unroll
    for (int i = 0; i < 8; i++) cf[i] = 0.0f;
    if (ux) {
        uint4 cr = *(const uint4*)(g_xp_h + ((size_t)b * NN + id0) * DOUT + c0);
        const __half2* ch = (const __half2*)&cr;
        #pragma unroll
        for (int i = 0; i < 4; i++) {
            float2 f = __half22float2(ch[i]);
            cf[2 * i] = f.x; cf[2 * i + 1] = f.y;
        }
    }

    uint4 a[4];
    #pragma unroll
    for (int q = 0; q < 4; q++)
        a[q] = make_uint4(0xFC00FC00u, 0xFC00FC00u, 0xFC00FC00u, 0xFC00FC00u);

    #pragma unroll
    for (int q = 0; q < 8; q++) {
        int4 iq = ((const int4*)myidx)[q];
        int j0 = iq.x < 0 ? id0 : iq.x;
        int j1 = iq.y < 0 ? id0 : iq.y;
        int j2 = iq.z < 0 ? id0 : iq.z;
        int j3 = iq.w < 0 ? id0 : iq.w;
        uint4 v0 = *(const uint4*)(sumb + (size_t)j0 * DOUT + c0);
        uint4 v1 = *(const uint4*)(sumb + (size_t)j1 * DOUT + c0);
        uint4 v2 = *(const uint4*)(sumb + (size_t)j2 * DOUT + c0);
        uint4 v3 = *(const uint4*)(sumb + (size_t)j3 * DOUT + c0);
        __half2* a0 = (__half2*)&a[0]; __half2* a1 = (__half2*)&a[1];
        __half2* a2 = (__half2*)&a[2]; __half2* a3 = (__half2*)&a[3];
        const __half2* h0 = (const __half2*)&v0;
        const __half2* h1 = (const __half2*)&v1;
        const __half2* h2 = (const __half2*)&v2;
        const __half2* h3 = (const __half2*)&v3;
        #pragma unroll
        for (int i = 0; i < 4; i++) {
            a0[i] = __hmax2(a0[i], h0[i]);
            a1[i] = __hmax2(a1[i], h1[i]);
            a2[i] = __hmax2(a2[i], h2[i]);
            a3[i] = __hmax2(a3[i], h3[i]);
        }
    }

    __half2* a0 = (__half2*)&a[0]; __half2* a1 = (__half2*)&a[1];
    __half2* a2 = (__half2*)&a[2]; __half2* a3 = (__half2*)&a[3];
    float of[8];
    #pragma unroll
    for (int i = 0; i < 4; i++) {
        __half2 m = __hmax2(__hmax2(a0[i], a1[i]), __hmax2(a2[i], a3[i]));
        float2 f = __half22float2(m);
        of[2 * i]     = f.x - cf[2 * i];
        of[2 * i + 1] = f.y - cf[2 * i + 1];
    }

    float* dst = out + p * DOUT + c0;
    *(float4*)dst       = make_float4(of[0], of[1], of[2], of[3]);
    *(float4*)(dst + 4) = make_float4(of[4], of[5], of[6], of[7]);
}

// ---------------------------------------------------------------------------
// Launcher: proj then pool with programmatic stream serialization (R12).
// ---------------------------------------------------------------------------
extern "C" void kernel_launch(void* const* d_in, const int* in_sizes, int n_in,
                              void* d_out, int out_size)
{
    const float* x    = (const float*)d_in[0];
    const float* xcm  = (const float*)d_in[1];
    const void*  idx  = d_in[2];
    const float* w1   = (const float*)d_in[3];
    const float* w2   = (const float*)d_in[4];
    const float* bias = (const float*)d_in[5];
    const int*   ux   = (const int*)d_in[6];
    float* out = (float*)d_out;

    cudaFuncSetAttribute(proj_mma, cudaFuncAttributeMaxDynamicSharedMemorySize, SMEM_ALLOC);

    proj_mma<<<(BB * NN) / 128, 256, SMEM_ALLOC>>>(x, xcm, w1, w2, bias, ux);

    cudaLaunchConfig_t cfg = {};
    cfg.gridDim  = dim3((BB * SS) / 32, 1, 1);
    cfg.blockDim = dim3(256, 1, 1);
    cfg.dynamicSmemBytes = 0;
    cfg.stream = 0;
    cudaLaunchAttribute attrs[1];
    attrs[0].id = cudaLaunchAttributeProgrammaticStreamSerialization;
    attrs[0].val.programmaticStreamSerializationAllowed = 1;
    cfg.attrs = attrs;
    cfg.numAttrs = 1;

    cudaError_t e = cudaLaunchKernelEx(&cfg, pool_kernel,
                                       (const void*)idx, ux, out);
    if (e != cudaSuccess) {
        pool_kernel<<<(BB * SS) / 32, 256>>>(idx, ux, out);
    }
}

// round 17
// speedup vs baseline: 1.3586x; 1.3586x over previous
#include <cuda_runtime.h>
#include <cuda_fp16.h>
#include <cstdint>

// Problem constants (fixed by the dataset)
#define BB   16
#define NN   4096
#define SS   1024
#define KK   32
#define DIN  64
#define DINC 67
#define DOUT 64

// Scratch (fp16 intermediates)
__device__ uint16_t g_sum_h[(size_t)BB * NN * DOUT];   // fp16(xc@W1 + bias (+ xp))
__device__ uint16_t g_xp_h [(size_t)BB * NN * DOUT];   // fp16(x@W2)

// ---------------------------------------------------------------------------
// SMEM layout (bytes)  [proj: 128 rows/CTA, R12 config -> occ 4, 32 warps/SM]
// ---------------------------------------------------------------------------
#define SAB   0                         // 9*128*32 = 36864
#define SBB   36864                     // 9*64*32  = 18432
#define SBIAS 55296                     // 256
#define SMEM_BYTES 55552

__device__ __forceinline__ uint32_t pack_h2(float v0, float v1) {
    __half2 h = __floats2half2_rn(v0, v1);
    return *(uint32_t*)&h;
}

__device__ __forceinline__ void mma16(float* d, uint32_t a0, uint32_t a1, uint32_t a2,
                                      uint32_t a3, uint32_t b0, uint32_t b1) {
    asm volatile(
        "mma.sync.aligned.m16n8k16.row.col.f32.f16.f16.f32 "
        "{%0,%1,%2,%3}, {%4,%5,%6,%7}, {%8,%9}, {%0,%1,%2,%3};"
        : "+f"(d[0]), "+f"(d[1]), "+f"(d[2]), "+f"(d[3])
        : "r"(a0), "r"(a1), "r"(a2), "r"(a3), "r"(b0), "r"(b1));
}

__device__ __forceinline__ void gemm_phase(
    const uint2* abuf, const uint2* bbuf, int ks0, int ks1,
    float acc[2][4][4], const int rA[2], const int nI[4], int km)
{
    for (int ks = ks0; ks < ks1; ks++) {
        uint2 A0[2], A1[2], Bv[4];
        #pragma unroll
        for (int tM = 0; tM < 2; tM++) {
            int r0 = rA[tM], r1 = rA[tM] + 8;
            A0[tM] = abuf[(ks * 128 + r0) * 4 + (km ^ (r0 & 3))];
            A1[tM] = abuf[(ks * 128 + r1) * 4 + (km ^ (r1 & 3))];
        }
        #pragma unroll
        for (int tN = 0; tN < 4; tN++) {
            int n = nI[tN];
            Bv[tN] = bbuf[(ks * 64 + n) * 4 + (km ^ (n & 3))];
        }
        #pragma unroll
        for (int tM = 0; tM < 2; tM++)
            #pragma unroll
            for (int tN = 0; tN < 4; tN++)
                mma16(acc[tM][tN], A0[tM].x, A1[tM].x, A0[tM].y, A1[tM].y, Bv[tN].x, Bv[tN].y);
    }
}

// ---------------------------------------------------------------------------
// proj_mma: per CTA computes 128 rows of g_xp_h and g_sum_h via fp16 MMA.
// R12 structure; float2 staging loads on 8B-aligned rows (W2, x).
// ---------------------------------------------------------------------------
__global__ void __launch_bounds__(256) proj_mma(
    const float* __restrict__ x, const float* __restrict__ xcm,
    const float* __restrict__ w1, const float* __restrict__ w2,
    const float* __restrict__ bias, const int* __restrict__ use_x)
{
    extern __shared__ char smem[];
    uint32_t* sA = (uint32_t*)(smem + SAB);
    uint32_t* sB = (uint32_t*)(smem + SBB);
    float*    sBias = (float*)(smem + SBIAS);

    const int tid  = threadIdx.x;
    const int wid  = tid >> 5;
    const int lane = tid & 31;
    const int ux   = use_x[0];
    const size_t base = (size_t)blockIdx.x * 128;

    // ---- stage W2 [64 n][64 k] -> B ks 0..3 (float2: rows 256B-aligned) ----
    for (int i = tid; i < 64 * 32; i += 256) {
        int n = i >> 5, jj32 = i & 31;
        int ks = jj32 >> 3, jj = jj32 & 7;
        int k0 = ks * 16 + 2 * jj;
        float2 w = *(const float2*)(w2 + n * DIN + k0);
        uint32_t p = pack_h2(w.x, w.y);
        int a2 = (ks * 64 + n) * 4 + ((jj & 3) ^ (n & 3));
        sB[a2 * 2 + (jj >> 2)] = p;
    }
    // ---- stage W1 [64 n][67 k -> 80] -> B ks 4..8 (scalar: odd row stride) --
    for (int i = tid; i < 64 * 40; i += 256) {
        int n = i / 40, jj40 = i - n * 40;
        int ksl = jj40 >> 3, jj = jj40 & 7;
        int k0 = ksl * 16 + 2 * jj;
        float v0 = (k0     < DINC) ? w1[n * DINC + k0]     : 0.0f;
        float v1 = (k0 + 1 < DINC) ? w1[n * DINC + k0 + 1] : 0.0f;
        uint32_t p = pack_h2(v0, v1);
        int ks = 4 + ksl;
        int a2 = (ks * 64 + n) * 4 + ((jj & 3) ^ (n & 3));
        sB[a2 * 2 + (jj >> 2)] = p;
    }
    if (tid < DOUT) sBias[tid] = bias[tid];
    // ---- stage x tile [128][64] -> A ks 0..3 (float2) ----
    if (ux) {
        const float* src = x + base * DIN;
        for (int i = tid; i < 128 * 32; i += 256) {
            int r = i >> 5, jj32 = i & 31;
            int ks = jj32 >> 3, jj = jj32 & 7;
            int k0 = ks * 16 + 2 * jj;
            float2 w = *(const float2*)(src + r * DIN + k0);
            uint32_t p = pack_h2(w.x, w.y);
            int a2 = (ks * 128 + r) * 4 + ((jj & 3) ^ (r & 3));
            sA[a2 * 2 + (jj >> 2)] = p;
        }
    }
    // ---- stage xc tile [128][67 -> 80] -> A ks 4..8 (scalar) ----
    {
        const float* src = xcm + base * DINC;
        for (int i = tid; i < 128 * 40; i += 256) {
            int r = i / 40, jj40 = i - r * 40;
            int ksl = jj40 >> 3, jj = jj40 & 7;
            int k0 = ksl * 16 + 2 * jj;
            float v0 = (k0     < DINC) ? src[r * DINC + k0]     : 0.0f;
            float v1 = (k0 + 1 < DINC) ? src[r * DINC + k0 + 1] : 0.0f;
            uint32_t p = pack_h2(v0, v1);
            int ks = 4 + ksl;
            int a2 = (ks * 128 + r) * 4 + ((jj & 3) ^ (r & 3));
            sA[a2 * 2 + (jj >> 2)] = p;
        }
    }
    __syncthreads();

    // ---- per-warp fragment coordinates (warp grid 4M x 2N; 32x32 per warp) --
    const int warpM = wid >> 1;
    const int warpN = wid & 1;
    const int km    = lane & 3;
    const int qr    = lane >> 2;
    int rA[2], nI[4];
    #pragma unroll
    for (int tM = 0; tM < 2; tM++) rA[tM] = warpM * 32 + tM * 16 + qr;
    #pragma unroll
    for (int tN = 0; tN < 4; tN++) nI[tN] = warpN * 32 + tN * 8 + qr;

    float acc[2][4][4];
    #pragma unroll
    for (int i = 0; i < 2; i++)
        #pragma unroll
        for (int j = 0; j < 4; j++)
            #pragma unroll
            for (int q = 0; q < 4; q++) acc[i][j][q] = 0.0f;

    const int colq = 2 * (lane & 3);

    // ---- Phase A: acc = x @ W2^T ; write g_xp_h ----
    if (ux) {
        gemm_phase((const uint2*)sA, (const uint2*)sB, 0, 4, acc, rA, nI, km);
        #pragma unroll
        for (int tM = 0; tM < 2; tM++) {
            int r = rA[tM];
            #pragma unroll
            for (int tN = 0; tN < 4; tN++) {
                int cc = warpN * 32 + tN * 8 + colq;
                uint16_t* p = g_xp_h + (base + r) * DOUT + cc;
                *(uint32_t*)p = pack_h2(acc[tM][tN][0], acc[tM][tN][1]);
                *(uint32_t*)(p + 8 * DOUT) = pack_h2(acc[tM][tN][2], acc[tM][tN][3]);
            }
        }
    }

    // ---- Phase B: acc += xc @ W1^T ; write g_sum_h = fp16(acc + bias) ----
    gemm_phase((const uint2*)sA, (const uint2*)sB, 4, 9, acc, rA, nI, km);

    #pragma unroll
    for (int tM = 0; tM < 2; tM++) {
        int r = rA[tM];
        #pragma unroll
        for (int tN = 0; tN < 4; tN++) {
            int cc = warpN * 32 + tN * 8 + colq;
            float2 bv = *(const float2*)(sBias + cc);
            uint16_t* p = g_sum_h + (base + r) * DOUT + cc;
            *(uint32_t*)p = pack_h2(acc[tM][tN][0] + bv.x, acc[tM][tN][1] + bv.y);
            *(uint32_t*)(p + 8 * DOUT) = pack_h2(acc[tM][tN][2] + bv.x, acc[tM][tN][3] + bv.y);
        }
    }
}

// ---------------------------------------------------------------------------
// Pool kernel (R12 optimum: 32 pairs/block, 8 threads/pair, uint4 + __hmax2)
// ---------------------------------------------------------------------------
__global__ void __launch_bounds__(256) pool_kernel(
    const void* __restrict__ indexes, const int* __restrict__ use_x,
    float* __restrict__ out)
{
    __shared__ int sidx[1024];          // 32 pairs x 32 idx
    const int tid = threadIdx.x;
    const size_t blk = blockIdx.x;      // 512 blocks

    // prologue: independent of proj output (in-bounds under BOTH dtypes)
    int4 v = ((const int4*)indexes)[blk * 256 + tid];
    bool pok = (v.y == (v.x < 0 ? -1 : 0)) && (v.w == (v.z < 0 ? -1 : 0));
    int is64 = __syncthreads_and(pok);

    if (is64) {
        longlong2 q0 = ((const longlong2*)indexes)[blk * 512 + 2 * tid];
        longlong2 q1 = ((const longlong2*)indexes)[blk * 512 + 2 * tid + 1];
        sidx[4 * tid]     = (int)q0.x;
        sidx[4 * tid + 1] = (int)q0.y;
        sidx[4 * tid + 2] = (int)q1.x;
        sidx[4 * tid + 3] = (int)q1.y;
    } else {
        sidx[4 * tid]     = v.x;
        sidx[4 * tid + 1] = v.y;
        sidx[4 * tid + 2] = v.z;
        sidx[4 * tid + 3] = v.w;
    }
    const int ux = use_x[0];
    __syncthreads();

    const int grp   = tid >> 3;
    const int lane8 = tid & 7;
    const size_t p  = blk * 32 + grp;
    const int b     = (int)(p >> 10);
    const int* myidx = sidx + grp * 32;
    const int c0  = lane8 * 8;
    const int id0 = myidx[0];

    // wait for proj grid completion (PDL)
    asm volatile("griddepcontrol.wait;" ::: "memory");

    const uint16_t* sumb = g_sum_h + (size_t)b * NN * DOUT;

    float cf[8];
    #pragma unroll
    for (int i = 0; i < 8; i++) cf[i] = 0.0f;
    if (ux) {
        uint4 cr = *(const uint4*)(g_xp_h + ((size_t)b * NN + id0) * DOUT + c0);
        const __half2* ch = (const __half2*)&cr;
        #pragma unroll
        for (int i = 0; i < 4; i++) {
            float2 f = __half22float2(ch[i]);
            cf[2 * i] = f.x; cf[2 * i + 1] = f.y;
        }
    }

    uint4 a[4];
    #pragma unroll
    for (int q = 0; q < 4; q++)
        a[q] = make_uint4(0xFC00FC00u, 0xFC00FC00u, 0xFC00FC00u, 0xFC00FC00u);

    #pragma unroll
    for (int q = 0; q < 8; q++) {
        int4 iq = ((const int4*)myidx)[q];
        int j0 = iq.x < 0 ? id0 : iq.x;
        int j1 = iq.y < 0 ? id0 : iq.y;
        int j2 = iq.z < 0 ? id0 : iq.z;
        int j3 = iq.w < 0 ? id0 : iq.w;
        uint4 v0 = *(const uint4*)(sumb + (size_t)j0 * DOUT + c0);
        uint4 v1 = *(const uint4*)(sumb + (size_t)j1 * DOUT + c0);
        uint4 v2 = *(const uint4*)(sumb + (size_t)j2 * DOUT + c0);
        uint4 v3 = *(const uint4*)(sumb + (size_t)j3 * DOUT + c0);
        __half2* a0 = (__half2*)&a[0]; __half2* a1 = (__half2*)&a[1];
        __half2* a2 = (__half2*)&a[2]; __half2* a3 = (__half2*)&a[3];
        const __half2* h0 = (const __half2*)&v0;
        const __half2* h1 = (const __half2*)&v1;
        const __half2* h2 = (const __half2*)&v2;
        const __half2* h3 = (const __half2*)&v3;
        #pragma unroll
        for (int i = 0; i < 4; i++) {
            a0[i] = __hmax2(a0[i], h0[i]);
            a1[i] = __hmax2(a1[i], h1[i]);
            a2[i] = __hmax2(a2[i], h2[i]);
            a3[i] = __hmax2(a3[i], h3[i]);
        }
    }

    __half2* a0 = (__half2*)&a[0]; __half2* a1 = (__half2*)&a[1];
    __half2* a2 = (__half2*)&a[2]; __half2* a3 = (__half2*)&a[3];
    float of[8];
    #pragma unroll
    for (int i = 0; i < 4; i++) {
        __half2 m = __hmax2(__hmax2(a0[i], a1[i]), __hmax2(a2[i], a3[i]));
        float2 f = __half22float2(m);
        of[2 * i]     = f.x - cf[2 * i];
        of[2 * i + 1] = f.y - cf[2 * i + 1];
    }

    float* dst = out + p * DOUT + c0;
    *(float4*)dst       = make_float4(of[0], of[1], of[2], of[3]);
    *(float4*)(dst + 4) = make_float4(of[4], of[5], of[6], of[7]);
}

// ---------------------------------------------------------------------------
// Launcher: proj then pool with programmatic stream serialization (R12).
// ---------------------------------------------------------------------------
extern "C" void kernel_launch(void* const* d_in, const int* in_sizes, int n_in,
                              void* d_out, int out_size)
{
    const float* x    = (const float*)d_in[0];
    const float* xcm  = (const float*)d_in[1];
    const void*  idx  = d_in[2];
    const float* w1   = (const float*)d_in[3];
    const float* w2   = (const float*)d_in[4];
    const float* bias = (const float*)d_in[5];
    const int*   ux   = (const int*)d_in[6];
    float* out = (float*)d_out;

    cudaFuncSetAttribute(proj_mma, cudaFuncAttributeMaxDynamicSharedMemorySize, SMEM_BYTES);

    proj_mma<<<(BB * NN) / 128, 256, SMEM_BYTES>>>(x, xcm, w1, w2, bias, ux);

    cudaLaunchConfig_t cfg = {};
    cfg.gridDim  = dim3((BB * SS) / 32, 1, 1);
    cfg.blockDim = dim3(256, 1, 1);
    cfg.dynamicSmemBytes = 0;
    cfg.stream = 0;
    cudaLaunchAttribute attrs[1];
    attrs[0].id = cudaLaunchAttributeProgrammaticStreamSerialization;
    attrs[0].val.programmaticStreamSerializationAllowed = 1;
    cfg.attrs = attrs;
    cfg.numAttrs = 1;

    cudaError_t e = cudaLaunchKernelEx(&cfg, pool_kernel,
                                       (const void*)idx, ux, out);
    if (e != cudaSuccess) {
        pool_kernel<<<(BB * SS) / 32, 256>>>(idx, ux, out);
    }
}